// round 2
// baseline (speedup 1.0000x reference)
#include <cuda_runtime.h>

// 0: x [2,192,88,133] f32, 1: W_lin [133,24], 2: b_lin [24], 3: W_qkv [24,72],
// 4: b_qkv [72], 5: rpb [4,49,49], 6: W_proj [24,24], 7: b_proj [24]
// output: [2,192,88,24] f32

#define BB   2
#define HT   192
#define WD   88
#define FIN  133
#define CC   24
#define NH   4
#define DH   6
#define WIN  25
#define NPIX (BB*HT*WD)   // 33792
#define RPBW (2*WIN - 1)  // 49

// Scratch (device globals: allocation-free)
__device__ float g_h[NPIX*CC];
__device__ float g_q[NPIX*CC];   // [b][row][ch(=h*6+d)][col]
__device__ float g_k[NPIX*CC];
__device__ float g_v[NPIX*CC];

// ---------------------------------------------------------------------------
// Kernel 1: h = relu(x @ W_lin + b_lin). 64 pixels/block, 6 outputs/thread.
// ---------------------------------------------------------------------------
__global__ void __launch_bounds__(256) k_linrelu(const float* __restrict__ x,
                                                 const float* __restrict__ W,
                                                 const float* __restrict__ b) {
    __shared__ float xs[64][FIN];       // 8512 f
    __shared__ float ws[FIN*CC];        // 3192 f
    int tid = threadIdx.x;
    int blk = blockIdx.x;               // 528 blocks
    int cg = tid & 3, p = tid >> 2;     // cg: group of 6 channels, p: pixel

    const float* xbase = x + (size_t)blk * 64 * FIN;
    for (int idx = tid; idx < 64*FIN; idx += 256)
        xs[idx / FIN][idx % FIN] = xbase[idx];
    for (int idx = tid; idx < FIN*CC; idx += 256)
        ws[idx] = W[idx];
    __syncthreads();

    float acc[6];
    #pragma unroll
    for (int t = 0; t < 6; ++t) acc[t] = b[cg*6 + t];

    #pragma unroll 7
    for (int f = 0; f < FIN; ++f) {
        float xf = xs[p][f];
        const float* wr = ws + f*CC + cg*6;
        #pragma unroll
        for (int t = 0; t < 6; ++t) acc[t] = fmaf(xf, wr[t], acc[t]);
    }

    float* out = g_h + ((size_t)(blk*64 + p) * CC) + cg*6;
    #pragma unroll
    for (int t = 0; t < 6; ++t) out[t] = fmaxf(acc[t], 0.0f);
}

// ---------------------------------------------------------------------------
// Kernel 2: qkv per (b,i) row. W column in registers, h reads broadcast,
// smem-transposed coalesced stores. q pre-scaled; q/k/v written d-major.
// ---------------------------------------------------------------------------
__global__ void __launch_bounds__(288) k_qkv(const float* __restrict__ Wq,
                                             const float* __restrict__ bq) {
    __shared__ float hs[WD][CC + 1];    // 2200 f (stride 25, conflict-free)
    __shared__ float ws[CC*3*CC];       // 1728 f
    __shared__ float outs[3*CC][WD];    // 6336 f
    int bi  = blockIdx.x;               // b*192 + i
    int tid = threadIdx.x;              // 288 = 72 cfull x 4 jg

    for (int idx = tid; idx < WD*CC; idx += 288)
        hs[idx / CC][idx % CC] = g_h[(size_t)bi * WD * CC + idx];
    for (int idx = tid; idx < CC*3*CC; idx += 288)
        ws[idx] = Wq[idx];
    __syncthreads();

    int cfull = tid % 72, jg = tid / 72;
    float w[CC];
    #pragma unroll
    for (int u = 0; u < CC; ++u) w[u] = ws[u*72 + cfull];
    float bias = bq[cfull];
    float scale = (cfull < CC) ? 0.40824829046386302f : 1.0f;

    #pragma unroll 2
    for (int jj = 0; jj < 22; ++jj) {
        int j = jg * 22 + jj;
        float acc = bias;
        #pragma unroll
        for (int u = 0; u < CC; ++u) acc = fmaf(hs[j][u], w[u], acc);
        outs[cfull][j] = acc * scale;
    }
    __syncthreads();

    // coalesced stores: each of q/k/v is [ch][col] contiguous per (bi,ch)
    for (int idx = tid; idx < 3*CC*WD; idx += 288) {
        int cf = idx / WD, j = idx % WD;
        int which = cf / CC, ch = cf % CC;
        float* dst = (which == 0) ? g_q : (which == 1) ? g_k : g_v;
        dst[((size_t)bi * CC + ch) * WD + j] = outs[cf][j];
    }
}

// ---------------------------------------------------------------------------
// Kernel 3: neighborhood attention + fused output projection.
// Block per (b,i); thread = (column-pair jp, head h); 2 queries/thread share
// the K/V smem reads over the union of their windows (25 or 26 columns).
// Online softmax, exp on MUFU (__expf) to keep the FMA pipe for dots.
// ---------------------------------------------------------------------------
template<int DELTA>
__device__ __forceinline__ void attn_step(
    const float* __restrict__ kbase, const float* __restrict__ vbase,
    const float* __restrict__ br0, const float* __restrict__ br1,
    const float* __restrict__ qv0, const float* __restrict__ qv1,
    float& m0, float& l0, float* acc0,
    float& m1, float& l1, float* acc1)
{
    float s0[WIN], s1[WIN];
    #pragma unroll
    for (int kj = 0; kj < WIN; ++kj) { s0[kj] = br0[kj]; s1[kj] = br1[kj]; }

    #pragma unroll
    for (int c = 0; c < WIN + DELTA; ++c) {
        float kc[DH];
        #pragma unroll
        for (int d = 0; d < DH; ++d) kc[d] = kbase[d*WD + c];
        float d0 = 0.f, d1 = 0.f;
        #pragma unroll
        for (int d = 0; d < DH; ++d) {
            d0 = fmaf(qv0[d], kc[d], d0);
            d1 = fmaf(qv1[d], kc[d], d1);
        }
        if (c < WIN)    s0[c]       += d0;
        if (c >= DELTA) s1[c-DELTA] += d1;
    }

    float r0 = s0[0], r1 = s1[0];
    #pragma unroll
    for (int kj = 1; kj < WIN; ++kj) { r0 = fmaxf(r0, s0[kj]); r1 = fmaxf(r1, s1[kj]); }
    float mn0 = fmaxf(m0, r0), mn1 = fmaxf(m1, r1);
    float cr0 = __expf(m0 - mn0), cr1 = __expf(m1 - mn1);
    l0 *= cr0; l1 *= cr1;
    #pragma unroll
    for (int d = 0; d < DH; ++d) { acc0[d] *= cr0; acc1[d] *= cr1; }

    #pragma unroll
    for (int kj = 0; kj < WIN; ++kj) {
        float p0 = __expf(s0[kj] - mn0); l0 += p0; s0[kj] = p0;
        float p1 = __expf(s1[kj] - mn1); l1 += p1; s1[kj] = p1;
    }

    #pragma unroll
    for (int c = 0; c < WIN + DELTA; ++c) {
        float vc[DH];
        #pragma unroll
        for (int d = 0; d < DH; ++d) vc[d] = vbase[d*WD + c];
        if (c < WIN) {
            float p = s0[c];
            #pragma unroll
            for (int d = 0; d < DH; ++d) acc0[d] = fmaf(p, vc[d], acc0[d]);
        }
        if (c >= DELTA) {
            float p = s1[c-DELTA];
            #pragma unroll
            for (int d = 0; d < DH; ++d) acc1[d] = fmaf(p, vc[d], acc1[d]);
        }
    }
    m0 = mn0; m1 = mn1;
}

__global__ void __launch_bounds__(176, 2) k_attn(const float* __restrict__ rpb,
                                                 const float* __restrict__ Wp,
                                                 const float* __restrict__ bp,
                                                 float* __restrict__ outp) {
    __shared__ float bias_s[NH * WIN * RPBW];  // 4900 f
    __shared__ float k_s[CC * WD];             // 2112 f (reused: attn out [88][24])
    __shared__ float v_s[CC * WD];             // 2112 f (reused: W_proj 576)

    int blk = blockIdx.x;
    int b = blk / HT, i = blk % HT;
    int tid = threadIdx.x;
    int jp = tid % 44, h = tid / 44;
    int j0 = 2*jp, j1 = j0 + 1;
    int h6 = h * DH;

    int sii  = min(max(i  - WIN/2, 0), HT - WIN);
    int bii  = sii - i + WIN - 1;
    int sjj0 = min(max(j0 - WIN/2, 0), WD - WIN);
    int sjj1 = min(max(j1 - WIN/2, 0), WD - WIN);
    int delta = sjj1 - sjj0;                   // 0 or 1
    int bjj0 = sjj0 - j0 + WIN - 1;
    int bjj1 = sjj1 - j1 + WIN - 1;

    for (int idx = tid; idx < NH*WIN*RPBW; idx += 176) {
        int hh = idx / (WIN*RPBW);
        bias_s[idx] = rpb[idx + hh * (RPBW*RPBW - WIN*RPBW) + bii * RPBW];
    }

    float qv0[DH], qv1[DH];
    const float* qb = g_q + ((size_t)(b*HT + i) * CC + h6) * WD;
    #pragma unroll
    for (int d = 0; d < DH; ++d) { qv0[d] = qb[d*WD + j0]; qv1[d] = qb[d*WD + j1]; }

    float m0 = -1e30f, m1 = -1e30f, l0 = 0.f, l1 = 0.f;
    float acc0[DH], acc1[DH];
    #pragma unroll
    for (int d = 0; d < DH; ++d) { acc0[d] = 0.f; acc1[d] = 0.f; }

    for (int ki = 0; ki < WIN; ++ki) {
        __syncthreads();
        size_t krow = ((size_t)(b*HT + sii + ki)) * CC * WD;
        #pragma unroll
        for (int u = 0; u < 12; ++u) {        // 2112 = 176*12 exact
            int idx = tid + u * 176;
            k_s[idx] = g_k[krow + idx];
            v_s[idx] = g_v[krow + idx];
        }
        __syncthreads();

        const float* kbase = k_s + h6*WD + sjj0;
        const float* vbase = v_s + h6*WD + sjj0;
        const float* br0 = bias_s + (h*WIN + ki)*RPBW + bjj0;
        const float* br1 = bias_s + (h*WIN + ki)*RPBW + bjj1;
        if (delta == 0)
            attn_step<0>(kbase, vbase, br0, br1, qv0, qv1, m0, l0, acc0, m1, l1, acc1);
        else
            attn_step<1>(kbase, vbase, br0, br1, qv0, qv1, m0, l0, acc0, m1, l1, acc1);
    }

    float inv0 = __fdividef(1.0f, l0);
    float inv1 = __fdividef(1.0f, l1);

    // ---- fused projection: stage attn out in k_s, W_proj in v_s ----
    __syncthreads();
    float* attn_s = k_s;                      // [88][24]
    #pragma unroll
    for (int d = 0; d < DH; ++d) {
        attn_s[j0*CC + h6 + d] = acc0[d] * inv0;
        attn_s[j1*CC + h6 + d] = acc1[d] * inv1;
    }
    float* wp_s = v_s;                        // 576 f
    for (int idx = tid; idx < CC*CC; idx += 176) wp_s[idx] = Wp[idx];
    __syncthreads();

    float* base = outp + (size_t)blk * WD * CC;
    for (int o = tid; o < WD*CC; o += 176) {
        int j = o / CC, c = o % CC;
        float a = bp[c];
        #pragma unroll
        for (int u = 0; u < CC; ++u) a = fmaf(attn_s[j*CC + u], wp_s[u*CC + c], a);
        base[o] = a;
    }
}

// ---------------------------------------------------------------------------
extern "C" void kernel_launch(void* const* d_in, const int* in_sizes, int n_in,
                              void* d_out, int out_size) {
    (void)in_sizes; (void)n_in; (void)out_size;
    const float* x      = (const float*)d_in[0];
    const float* W_lin  = (const float*)d_in[1];
    const float* b_lin  = (const float*)d_in[2];
    const float* W_qkv  = (const float*)d_in[3];
    const float* b_qkv  = (const float*)d_in[4];
    const float* rpb    = (const float*)d_in[5];
    const float* W_proj = (const float*)d_in[6];
    const float* b_proj = (const float*)d_in[7];
    float* out = (float*)d_out;

    float* g_h_ptr;
    cudaGetSymbolAddress((void**)&g_h_ptr, g_h);

    k_linrelu<<<NPIX/64, 256>>>(x, W_lin, b_lin);
    // layer 0 -> g_h, layer 1 -> d_out
    k_qkv <<<BB*HT, 288>>>(W_qkv, b_qkv);
    k_attn<<<BB*HT, 176>>>(rpb, W_proj, b_proj, g_h_ptr);
    k_qkv <<<BB*HT, 288>>>(W_qkv, b_qkv);
    k_attn<<<BB*HT, 176>>>(rpb, W_proj, b_proj, out);
}

// round 3
// speedup vs baseline: 2.4205x; 2.4205x over previous
#include <cuda_runtime.h>

// 0: x [2,192,88,133] f32, 1: W_lin [133,24], 2: b_lin [24], 3: W_qkv [24,72],
// 4: b_qkv [72], 5: rpb [4,49,49], 6: W_proj [24,24], 7: b_proj [24]
// output: [2,192,88,24] f32

#define BB   2
#define HT   192
#define WD   88
#define FIN  133
#define CC   24
#define NH   4
#define DH   6
#define WIN  25
#define NPIX (BB*HT*WD)   // 33792
#define RPBW (2*WIN - 1)  // 49
#define TR   3            // query rows per attn block
#define NT   352          // attn threads (88 cols x 4 heads)
#define BROWS 29          // staged bias rows per block
#define BH   (BROWS*RPBW) // 1421

// Scratch (device globals: allocation-free)
__device__ float g_h[NPIX*CC];
__device__ float g_q[NPIX*CC];   // [b][row][ch(=h*6+d)][col]
__device__ float g_k[NPIX*CC];
__device__ float g_v[NPIX*CC];

// ---------------------------------------------------------------------------
// Kernel 1: h = relu(x @ W_lin + b_lin). 64 pixels/block, 6 outputs/thread.
// ---------------------------------------------------------------------------
__global__ void __launch_bounds__(256) k_linrelu(const float* __restrict__ x,
                                                 const float* __restrict__ W,
                                                 const float* __restrict__ b) {
    __shared__ float xs[64][FIN];
    __shared__ float ws[FIN*CC];
    int tid = threadIdx.x;
    int blk = blockIdx.x;
    int cg = tid & 3, p = tid >> 2;

    const float* xbase = x + (size_t)blk * 64 * FIN;
    for (int idx = tid; idx < 64*FIN; idx += 256)
        xs[idx / FIN][idx % FIN] = xbase[idx];
    for (int idx = tid; idx < FIN*CC; idx += 256)
        ws[idx] = W[idx];
    __syncthreads();

    float acc[6];
    #pragma unroll
    for (int t = 0; t < 6; ++t) acc[t] = b[cg*6 + t];

    #pragma unroll 7
    for (int f = 0; f < FIN; ++f) {
        float xf = xs[p][f];
        const float* wr = ws + f*CC + cg*6;
        #pragma unroll
        for (int t = 0; t < 6; ++t) acc[t] = fmaf(xf, wr[t], acc[t]);
    }

    float* out = g_h + ((size_t)(blk*64 + p) * CC) + cg*6;
    #pragma unroll
    for (int t = 0; t < 6; ++t) out[t] = fmaxf(acc[t], 0.0f);
}

// ---------------------------------------------------------------------------
// Kernel 2: qkv per (b,i) row. W column in regs; 2 interleaved j-accumulators
// so the 24-deep FMA chain latency is overlapped. q pre-scaled; d-major out.
// ---------------------------------------------------------------------------
__global__ void __launch_bounds__(288) k_qkv(const float* __restrict__ Wq,
                                             const float* __restrict__ bq) {
    __shared__ float hs[WD][CC + 1];
    __shared__ float ws[CC*3*CC];
    __shared__ float outs[3*CC][WD];
    int bi  = blockIdx.x;
    int tid = threadIdx.x;              // 288 = 72 cfull x 4 jg

    for (int idx = tid; idx < WD*CC; idx += 288)
        hs[idx / CC][idx % CC] = g_h[(size_t)bi * WD * CC + idx];
    for (int idx = tid; idx < CC*3*CC; idx += 288)
        ws[idx] = Wq[idx];
    __syncthreads();

    int cfull = tid % 72, jg = tid / 72;
    float w[CC];
    #pragma unroll
    for (int u = 0; u < CC; ++u) w[u] = ws[u*72 + cfull];
    float bias = bq[cfull];
    float scale = (cfull < CC) ? 0.40824829046386302f : 1.0f;
    int jbase = jg * 22;

    #pragma unroll
    for (int jj = 0; jj < 11; ++jj) {
        int ja = jbase + jj, jb = jbase + jj + 11;
        float a0 = bias, a1 = bias;
        #pragma unroll
        for (int u = 0; u < CC; ++u) {
            float wu = w[u];
            a0 = fmaf(hs[ja][u], wu, a0);
            a1 = fmaf(hs[jb][u], wu, a1);
        }
        outs[cfull][ja] = a0 * scale;
        outs[cfull][jb] = a1 * scale;
    }
    __syncthreads();

    for (int idx = tid; idx < 3*CC*WD; idx += 288) {
        int cf = idx / WD, j = idx % WD;
        int which = cf / CC, ch = cf % CC;
        float* dst = (which == 0) ? g_q : (which == 1) ? g_k : g_v;
        dst[((size_t)bi * CC + ch) * WD + j] = outs[cf][j];
    }
}

// ---------------------------------------------------------------------------
// Kernel 3: attention over an i-triple + fused projection.
// Block = (b, i0..i0+2); thread = (j, h). 3 query rows share each K/V column
// read. Direct exp (center-score subtracted) -> no running max / rescale.
// ---------------------------------------------------------------------------
__device__ __forceinline__ void attn_row(
    const float* __restrict__ kb, const float* __restrict__ vb,
    const float* br0, const float* br1, const float* br2,
    const float (*qv)[DH], float* sc, float* l, float (*acc)[DH],
    float w0, float w1, float w2, bool allv)
{
    #pragma unroll
    for (int c = 0; c < WIN; ++c) {
        float kc[DH];
        #pragma unroll
        for (int d = 0; d < DH; ++d) kc[d] = kb[d*WD + c];
        float d0 = br0[c] - sc[0], d1 = br1[c] - sc[1], d2 = br2[c] - sc[2];
        #pragma unroll
        for (int d = 0; d < DH; ++d) {
            d0 = fmaf(qv[0][d], kc[d], d0);
            d1 = fmaf(qv[1][d], kc[d], d1);
            d2 = fmaf(qv[2][d], kc[d], d2);
        }
        float p0 = __expf(d0), p1 = __expf(d1), p2 = __expf(d2);
        if (!allv) { p0 *= w0; p1 *= w1; p2 *= w2; }
        l[0] += p0; l[1] += p1; l[2] += p2;
        float vc[DH];
        #pragma unroll
        for (int d = 0; d < DH; ++d) vc[d] = vb[d*WD + c];
        #pragma unroll
        for (int d = 0; d < DH; ++d) {
            acc[0][d] = fmaf(p0, vc[d], acc[0][d]);
            acc[1][d] = fmaf(p1, vc[d], acc[1][d]);
            acc[2][d] = fmaf(p2, vc[d], acc[2][d]);
        }
    }
}

__global__ void __launch_bounds__(NT) k_attn(const float* __restrict__ rpb,
                                             const float* __restrict__ Wp,
                                             const float* __restrict__ bp,
                                             float* __restrict__ outp) {
    __shared__ float smem[NH*BH + 2*CC*WD];   // 5684 + 4224 = 9908 f (39.6KB)
    float* bias_s = smem;                      // [4][29][49]
    float* k_s = smem + NH*BH;                 // 2112
    float* v_s = k_s + CC*WD;                  // 2112

    int blk = blockIdx.x;                      // 128 blocks
    int b = blk >> 6, it = blk & 63;
    int i0 = it * TR;
    int tid = threadIdx.x;
    int j = tid % WD, h = tid / WD;
    int h6 = h * DH;

    int sii[TR];
    #pragma unroll
    for (int t = 0; t < TR; ++t) sii[t] = min(max(i0 + t - WIN/2, 0), HT - WIN);
    int r_lo = sii[0], r_hi = sii[TR-1] + WIN - 1;
    int nrows = r_hi - r_lo + 1;               // 25..27
    int row_base = r_lo - (i0 + TR - 1) + WIN - 1;

    int sjj = min(max(j - WIN/2, 0), WD - WIN);
    int bjcol = sjj - j + WIN - 1;

    // stage 29 bias rows x 4 heads (rows clamped into [0,48])
    for (int idx = tid; idx < NH*BH; idx += NT) {
        int hh = idx / BH, rem = idx % BH;
        int rr = rem / RPBW, ccol = rem % RPBW;
        int src = min(max(row_base + rr, 0), RPBW - 1);
        bias_s[idx] = rpb[hh*RPBW*RPBW + src*RPBW + ccol];
    }

    // q vectors + center scores (center key = (i_t, j) itself, always in-window)
    float qv[TR][DH], sc[TR], l[TR], acc[TR][DH];
    #pragma unroll
    for (int t = 0; t < TR; ++t) {
        const float* qb = g_q + ((size_t)(b*HT + i0 + t) * CC + h6) * WD + j;
        const float* kc = g_k + ((size_t)(b*HT + i0 + t) * CC + h6) * WD + j;
        float s = 0.f;
        #pragma unroll
        for (int d = 0; d < DH; ++d) {
            qv[t][d] = qb[d*WD];
            s = fmaf(qv[t][d], kc[d*WD], s);
        }
        sc[t] = s; l[t] = 0.f;
        #pragma unroll
        for (int d = 0; d < DH; ++d) acc[t][d] = 0.f;
    }

    // prefetch first K/V row into registers
    float kr[6], vr[6];
    {
        size_t krow = ((size_t)(b*HT + r_lo)) * CC * WD;
        #pragma unroll
        for (int u = 0; u < 6; ++u) {
            kr[u] = g_k[krow + tid + u*NT];
            vr[u] = g_v[krow + tid + u*NT];
        }
    }

    for (int rr = 0; rr < nrows; ++rr) {
        int r = r_lo + rr;
        __syncthreads();
        #pragma unroll
        for (int u = 0; u < 6; ++u) {
            k_s[tid + u*NT] = kr[u];
            v_s[tid + u*NT] = vr[u];
        }
        __syncthreads();
        if (rr + 1 < nrows) {                 // prefetch next row during compute
            size_t krow = ((size_t)(b*HT + r + 1)) * CC * WD;
            #pragma unroll
            for (int u = 0; u < 6; ++u) {
                kr[u] = g_k[krow + tid + u*NT];
                vr[u] = g_v[krow + tid + u*NT];
            }
        }

        const float* kb = k_s + h6*WD + sjj;
        const float* vb = v_s + h6*WD + sjj;
        // bias row for query t at key row r: rr + (TR-1 - t)
        const float* brow = bias_s + h*BH + rr*RPBW + bjcol;
        const float* br0 = brow + 2*RPBW;
        const float* br1 = brow + 1*RPBW;
        const float* br2 = brow;

        bool v0 = (r >= sii[0]) & (r <= sii[0] + WIN - 1);
        bool v1 = (r >= sii[1]) & (r <= sii[1] + WIN - 1);
        bool v2 = (r >= sii[2]) & (r <= sii[2] + WIN - 1);
        if (v0 & v1 & v2)
            attn_row(kb, vb, br0, br1, br2, qv, sc, l, acc, 1.f, 1.f, 1.f, true);
        else
            attn_row(kb, vb, br0, br1, br2, qv, sc, l, acc,
                     v0 ? 1.f : 0.f, v1 ? 1.f : 0.f, v2 ? 1.f : 0.f, false);
    }

    // ---- fused projection ----
    __syncthreads();
    float* attn_s = smem;                      // [3][88][24] = 6336 f
    float* wp_s = smem + 6400;                 // 576 f
    #pragma unroll
    for (int t = 0; t < TR; ++t) {
        float inv = __fdividef(1.0f, l[t]);
        #pragma unroll
        for (int d = 0; d < DH; ++d)
            attn_s[(t*WD + j)*CC + h6 + d] = acc[t][d] * inv;
    }
    for (int idx = tid; idx < CC*CC; idx += NT) wp_s[idx] = Wp[idx];
    __syncthreads();

    float* base = outp + (size_t)(b*HT + i0) * WD * CC;
    for (int o = tid; o < TR*WD*CC; o += NT) {
        int c = o % CC;
        const float* ar = attn_s + (o / CC) * CC;
        float a = bp[c];
        #pragma unroll
        for (int u = 0; u < CC; ++u) a = fmaf(ar[u], wp_s[u*CC + c], a);
        base[o] = a;
    }
}

// ---------------------------------------------------------------------------
extern "C" void kernel_launch(void* const* d_in, const int* in_sizes, int n_in,
                              void* d_out, int out_size) {
    (void)in_sizes; (void)n_in; (void)out_size;
    const float* x      = (const float*)d_in[0];
    const float* W_lin  = (const float*)d_in[1];
    const float* b_lin  = (const float*)d_in[2];
    const float* W_qkv  = (const float*)d_in[3];
    const float* b_qkv  = (const float*)d_in[4];
    const float* rpb    = (const float*)d_in[5];
    const float* W_proj = (const float*)d_in[6];
    const float* b_proj = (const float*)d_in[7];
    float* out = (float*)d_out;

    float* g_h_ptr;
    cudaGetSymbolAddress((void**)&g_h_ptr, g_h);

    k_linrelu<<<NPIX/64, 256>>>(x, W_lin, b_lin);
    k_qkv <<<BB*HT, 288>>>(W_qkv, b_qkv);
    k_attn<<<BB*HT/TR, NT>>>(rpb, W_proj, b_proj, g_h_ptr);
    k_qkv <<<BB*HT, 288>>>(W_qkv, b_qkv);
    k_attn<<<BB*HT/TR, NT>>>(rpb, W_proj, b_proj, out);
}